// round 15
// baseline (speedup 1.0000x reference)
#include <cuda_runtime.h>

#define DIM 8192
typedef unsigned long long u64;

// ---- packed f32x2 helpers (SASS FFMA2/FMUL2 path, PTX-only) ----
__device__ __forceinline__ float2 f2fma(float2 a, float2 b, float2 c) {
    u64 r, au = *(u64*)&a, bu = *(u64*)&b, cu = *(u64*)&c;
    asm("fma.rn.f32x2 %0,%1,%2,%3;" : "=l"(r) : "l"(au), "l"(bu), "l"(cu));
    return *(float2*)&r;
}
__device__ __forceinline__ float2 f2mul(float2 a, float2 b) {
    u64 r, au = *(u64*)&a, bu = *(u64*)&b;
    asm("mul.rn.f32x2 %0,%1,%2;" : "=l"(r) : "l"(au), "l"(bu));
    return *(float2*)&r;
}
__device__ __forceinline__ float2 f2add(float2 a, float2 b) {
    u64 r, au = *(u64*)&a, bu = *(u64*)&b;
    asm("add.rn.f32x2 %0,%1,%2;" : "=l"(r) : "l"(au), "l"(bu));
    return *(float2*)&r;
}

// XOR-linear swizzle; bank(16B) = i0-2 ^ i4-6 ^ (i9<<1 | i10<<2).
// Conflict-free for all 6 structured access patterns below.
// XOR-linear over disjoint fields => phys(a|b) = phys(a) ^ phys(b).
__device__ constexpr int phys(int i) {
    return i ^ ((i >> 4) & 15) ^ ((i >> 8) & 6);
}

// Tangent-form RY rotation on register-bit BQ: out = (I + t*J) * in.
// Per-gate c = cos(theta/2) deferred into global C applied at measurement.
template<int BQ>
__device__ __forceinline__ void rotYt(float2 (&re)[16], float2 (&im)[16],
                                      float2 tg, float2 ntg) {
#pragma unroll
    for (int k0 = 0; k0 < 16; k0++) {
        if (k0 & (1 << BQ)) continue;
        const int k1 = k0 | (1 << BQ);
        const float2 r0 = re[k0], r1 = re[k1], i0 = im[k0], i1 = im[k1];
        re[k0] = f2fma(ntg, r1, r0);
        re[k1] = f2fma(tg,  r0, r1);
        im[k0] = f2fma(ntg, i1, i0);
        im[k1] = f2fma(tg,  i0, i1);
    }
}

__global__ void __launch_bounds__(512, 1)
qc_kernel(const float* __restrict__ x, const float* __restrict__ w,
          float* __restrict__ out)
{
    extern __shared__ float4 st[];                 // 8192 x (re-pack, im-pack) = 128 KB
    __shared__ float2 gt[26], gnt[26];             // tan(theta/2), packed dup (+/-)
    __shared__ float  gcs[26];                     // cos(theta/2) scalars
    __shared__ float  Csq;                         // (prod c_g)^2, precomputed
    __shared__ __align__(16) float2 tbl0s[16];     // A0 k-delta phases
    __shared__ __align__(16) float2 tbl1s[16];     // D01 k-delta (+Q,R) phases
    __shared__ float2 red[16], red2[16];

    const int t    = threadIdx.x;
    const int b    = blockIdx.x;                   // batch rows 2b, 2b+1
    const int lane = t & 31;
    const int warp = t >> 5;

    // ---- tables into smem (disjoint thread groups; visible after BAR1).
    // Fast sincos + fast divide: tan rel-err ~1e-6, compounded over 17 gates
    // ~4e-6 -- far below the 1e-3 budget. Cuts warp-0 skew at BAR1.
    if (t < 26) {
        const int l = t / 13, q = t - l * 13;
        float s, c; __sincosf(0.5f * __ldg(&w[l*39 + q*3 + 1]), &s, &c);
        const float tn = __fdividef(s, c);
        gt[t]  = make_float2( tn,  tn);
        gnt[t] = make_float2(-tn, -tn);
        gcs[t] = c;
    } else if (t >= 64 && t < 80) {                 // A0 delta: i bits 0-3 -> phi0_{12..9}
        const int k = t - 64;
        float ang = 0.f;
        if (k & 1) ang += __ldg(&w[36]);
        if (k & 2) ang += __ldg(&w[33]);
        if (k & 4) ang += __ldg(&w[30]);
        if (k & 8) ang += __ldg(&w[27]);
        float s, c; __sincosf(ang, &s, &c);
        tbl0s[k] = make_float2(c, s);
    } else if (t >= 96 && t < 112) {                // D01 delta: omega0_{3..0} + Q,R terms
        const int k = t - 96;
        float ang = 0.f;
        if (k & 1) ang += __ldg(&w[11]);
        if (k & 2) ang += __ldg(&w[8]);
        if (k & 4) ang += __ldg(&w[5]);
        if (k & 8) ang += __ldg(&w[2]);
        ang += (__popc(k & 14) & 1) ?  0.5f*__ldg(&w[45]) : -0.5f*__ldg(&w[45]);
        ang += (__popc(k & 12) & 1) ?  0.5f*__ldg(&w[42]) : -0.5f*__ldg(&w[42]);
        float s, c; __sincosf(ang, &s, &c);
        tbl1s[k] = make_float2(c, s);
    }

    // ---- load two rows (layout A1: i = (t<<4)|k). Normalization deferred. ----
    float2 re[16], im[16];
    const float4* xp0 = reinterpret_cast<const float4*>(x + (size_t)(2*b)   * DIM + (t << 4));
    const float4* xp1 = reinterpret_cast<const float4*>(x + (size_t)(2*b+1) * DIM + (t << 4));
    float2 ss = make_float2(0.f, 0.f);
#pragma unroll
    for (int k4 = 0; k4 < 4; k4++) {
        const float4 v0 = xp0[k4];
        const float4 v1 = xp1[k4];
        re[k4*4+0] = make_float2(v0.x, v1.x);
        re[k4*4+1] = make_float2(v0.y, v1.y);
        re[k4*4+2] = make_float2(v0.z, v1.z);
        re[k4*4+3] = make_float2(v0.w, v1.w);
    }
#pragma unroll
    for (int k = 0; k < 16; k++) ss = f2fma(re[k], re[k], ss);

    // ---- per-thread phase bases (overlaps x-LDG latency) ----
    float b0a = -0.5f*(__ldg(&w[27]) + __ldg(&w[30]) + __ldg(&w[33]) + __ldg(&w[36]));
#pragma unroll
    for (int q = 0; q < 9; q++) {
        const float ph = __ldg(&w[3*q]);
        b0a += ((t >> (8 - q)) & 1) ? 0.5f*ph : -0.5f*ph;
    }
    float sb0, cb0; __sincosf(b0a, &sb0, &cb0);

    const int pt = (lane << 4) | warp;
    float bBa = -0.5f*(__ldg(&w[2]) + __ldg(&w[5]) + __ldg(&w[8]) + __ldg(&w[11]));
#pragma unroll
    for (int bb = 0; bb < 9; bb++) {
        const float om = __ldg(&w[3*(12 - bb) + 2]);
        bBa += ((pt >> bb) & 1) ? 0.5f*om : -0.5f*om;
    }
    const int PM[10] = {511,510,508,504,496,480,448,384,256,0};
    float Pv = 0.f;
#pragma unroll
    for (int tt = 0; tt < 10; tt++) {
        const float ph = __ldg(&w[75 - 3*tt]);
        Pv += (__popc(PM[tt] & pt) & 1) ? 0.5f*ph : -0.5f*ph;
    }
    const float Sv = (__popc(pt) & 1) ? 0.5f*__ldg(&w[39]) : -0.5f*__ldg(&w[39]);
    float sB, cB; __sincosf(bBa, &sB, &cB);
    float sP, cP; __sincosf(Pv,  &sP, &cP);
    float sS, cS; __sincosf(Sv,  &sS, &cS);
    const float t1r = cB*cP - sB*sP, t1i = cB*sP + sB*cP;
    const float t2r = cB*cP + sB*sP, t2i = sB*cP - cB*sP;
    const float w00r = t1r*cS - t1i*sS, w00i = t1r*sS + t1i*cS;
    const float w01r = t1r*cS + t1i*sS, w01i = t1i*cS - t1r*sS;
    const float w10r = t2r*cS - t2i*sS, w10i = t2r*sS + t2i*cS;
    const float w11r = t2r*cS + t2i*sS, w11i = t2i*cS - t2r*sS;

    // XOR-linear swizzled address bases (one LOP3 per access in the loops)
    const int pA1 = phys(t << 4);                                   // A1 store
    const int pA2 = phys((warp << 9) | ((lane & 16) << 4) | (lane & 15)); // A2 ld / C' st
    const int pCp = phys(pt);                                       // C' ld / L2 st
    const int pL2 = phys(((lane >> 1) << 9) | ((lane & 1) << 4) | warp); // L2 ld

    __syncthreads();   // BAR 1: tables visible (hidden under x-load latency)

    // Precompute C^2 off the critical tail (idle warp 14; ordered by BAR3)
    if (t == 448) {
        float C = 1.f;
#pragma unroll
        for (int g = 0; g < 13; g++) C *= gcs[g];
        C *= gcs[13] * gcs[15] * gcs[17] * gcs[19];
        Csq = C * C;
    }

    // ---- A0: layer-0 phi phase on the (unnormalized) real input ----
    const float4* tbl0f4 = reinterpret_cast<const float4*>(tbl0s);
#pragma unroll
    for (int kk = 0; kk < 8; kk++) {
        const float4 tb = tbl0f4[kk];
        {
            const int k0 = 2*kk;
            const float vr = cb0*tb.x - sb0*tb.y;
            const float vi = cb0*tb.y + sb0*tb.x;
            const float2 x0 = re[k0];
            re[k0] = f2mul(x0, make_float2(vr, vr));
            im[k0] = f2mul(x0, make_float2(vi, vi));
        }
        {
            const int k1 = 2*kk + 1;
            const float vr = cb0*tb.z - sb0*tb.w;
            const float vi = cb0*tb.w + sb0*tb.z;
            const float2 x1 = re[k1];
            re[k1] = f2mul(x1, make_float2(vr, vr));
            im[k1] = f2mul(x1, make_float2(vi, vi));
        }
    }

    // ==== LAYER 0 (tangent form) ====
    // pass A1: reg bits = i bits 0-3 (qubits 12..9)
    rotYt<0>(re, im, gt[12], gnt[12]);
    rotYt<1>(re, im, gt[11], gnt[11]);
    rotYt<2>(re, im, gt[10], gnt[10]);
    rotYt<3>(re, im, gt[ 9], gnt[ 9]);

    // warp-local exchange A1 -> A2 (reg bits = i bits 4-7)
#pragma unroll
    for (int k = 0; k < 16; k++)
        st[pA1 ^ phys(k)] = make_float4(re[k].x, re[k].y, im[k].x, im[k].y);
    __syncwarp();
#pragma unroll
    for (int k = 0; k < 16; k++) {
        const float4 v = st[pA2 ^ phys(k << 4)];
        re[k] = make_float2(v.x, v.y); im[k] = make_float2(v.z, v.w);
    }
    rotYt<0>(re, im, gt[8], gnt[8]);
    rotYt<1>(re, im, gt[7], gnt[7]);
    rotYt<2>(re, im, gt[6], gnt[6]);
    rotYt<3>(re, im, gt[5], gnt[5]);
    // shfl gate on i bit 8 (= lane bit 4), qubit 4
    {
        const float2 tSel = (lane & 16) ? gt[4] : gnt[4];
#pragma unroll
        for (int k = 0; k < 16; k++) {
            const u64 pr = __shfl_xor_sync(0xffffffffu, *(u64*)&re[k], 16);
            const u64 pi = __shfl_xor_sync(0xffffffffu, *(u64*)&im[k], 16);
            re[k] = f2fma(tSel, *(const float2*)&pr, re[k]);
            im[k] = f2fma(tSel, *(const float2*)&pi, im[k]);
        }
    }

    // block exchange A2 -> C' : i = (k<<9) | pt
#pragma unroll
    for (int k = 0; k < 16; k++)
        st[pA2 ^ phys(k << 4)] = make_float4(re[k].x, re[k].y, im[k].x, im[k].y);
    __syncthreads();                                             // BAR 2
#pragma unroll
    for (int k = 0; k < 16; k++) {
        const float4 v = st[pCp ^ phys(k << 9)];
        re[k] = make_float2(v.x, v.y); im[k] = make_float2(v.z, v.w);
    }
    // pass C': reg bits = i bits 9-12 (qubits 3..0)
    rotYt<0>(re, im, gt[3], gnt[3]);
    rotYt<1>(re, im, gt[2], gnt[2]);
    rotYt<2>(re, im, gt[1], gnt[1]);
    rotYt<3>(re, im, gt[0], gnt[0]);

    // ==== D01 diagonal: V[k] = W[s1(k)][s2(k)] * tbl1s[k] (selects fold at compile time) ====
    const float4* tbl1f4 = reinterpret_cast<const float4*>(tbl1s);
#pragma unroll
    for (int kk = 0; kk < 8; kk++) {
        const float4 tb = tbl1f4[kk];
#pragma unroll
        for (int h = 0; h < 2; h++) {
            const int k = 2*kk + h;
            const float tr_ = h ? tb.z : tb.x;
            const float ti_ = h ? tb.w : tb.y;
            const int s1 = __popc(k) & 1;
            const int s2 = __popc(k & 7) & 1;
            const float wr = s1 ? (s2 ? w11r : w10r) : (s2 ? w01r : w00r);
            const float wi = s1 ? (s2 ? w11i : w10i) : (s2 ? w01i : w00i);
            const float vr = wr*tr_ - wi*ti_;
            const float vi = wr*ti_ + wi*tr_;
            const float2 cd = make_float2(vr, vr);
            const float2 sd = make_float2(vi, vi);
            const float2 nd = make_float2(-vi, -vi);
            const float2 nr = f2fma(cd, re[k], f2mul(nd, im[k]));
            const float2 ni = f2fma(sd, re[k], f2mul(cd, im[k]));
            re[k] = nr; im[k] = ni;
        }
    }

    // ==== LAYER 1 (tangent form) ====
    // d12 = {11,12} (k-mask 12 in C'), orient = parity(i & 4095) : gate 13 (qubit 0)
    {
        const int Pt = __popc(pt) & 1;
        const float2 tP  = Pt ? gt[13] : gnt[13];   // coeff when popc(k0&7) even
        const float2 tPn = Pt ? gnt[13] : gt[13];
#pragma unroll
        for (int k0 = 0; k0 < 8; k0++) {
            const int k1 = k0 ^ 12;
            const int e = __popc(k0 & 7) & 1;       // compile-time
            const float2 ta_ = e ? tPn : tP;
            const float2 tb_ = e ? tP  : tPn;
            const float2 ar = re[k0], ai = im[k0], br = re[k1], bi = im[k1];
            re[k0] = f2fma(ta_, br, ar);
            im[k0] = f2fma(ta_, bi, ai);
            re[k1] = f2fma(tb_, ar, br);
            im[k1] = f2fma(tb_, ai, bi);
        }
    }
    // d10 = {9,10} (k-mask 3 in C'), orient = parity(k & 14) : gate 15 (qubit 2)
    {
#pragma unroll
        for (int k0 = 0; k0 < 16; k0++) {
            if ((k0 & 3) > 1) continue;
            const int k1 = k0 ^ 3;
            const int o = __popc(k0 & 14) & 1;      // compile-time
            const float2 ta_ = o ? gt[15] : gnt[15];
            const float2 tb_ = o ? gnt[15] : gt[15];
            const float2 ar = re[k0], ai = im[k0], br = re[k1], bi = im[k1];
            re[k0] = f2fma(ta_, br, ar);
            im[k0] = f2fma(ta_, bi, ai);
            re[k1] = f2fma(tb_, ar, br);
            im[k1] = f2fma(tb_, ai, bi);
        }
    }

    // ==== warp-local exchange C' -> L2 (warp-private slots; syncwarp only) ====
    // L2: reg k = i bits 5-8; lane bit0 = i4, lane bits 1-4 = i bits 9-12
#pragma unroll
    for (int k = 0; k < 16; k++)
        st[pCp ^ phys(k << 9)] = make_float4(re[k].x, re[k].y, im[k].x, im[k].y);
    __syncwarp();
#pragma unroll
    for (int k = 0; k < 16; k++) {
        const float4 v = st[pL2 ^ phys(k << 5)];
        re[k] = make_float2(v.x, v.y); im[k] = make_float2(v.z, v.w);
    }

    // d8 = {7,8} (k-mask 12 in L2), orient = i8 ^ parity(i9-12) : gate 17 (qubit 4)
    {
        const int oL = __popc(lane & 30) & 1;
        const float2 ta_ = oL ? gt[17] : gnt[17];
        const float2 tb_ = oL ? gnt[17] : gt[17];
#pragma unroll
        for (int k0 = 0; k0 < 8; k0++) {
            const int k1 = k0 ^ 12;
            const float2 ar = re[k0], ai = im[k0], br = re[k1], bi = im[k1];
            re[k0] = f2fma(ta_, br, ar);
            im[k0] = f2fma(ta_, bi, ai);
            re[k1] = f2fma(tb_, ar, br);
            im[k1] = f2fma(tb_, ai, bi);
        }
    }
    // d6 = {5,6} (k-mask 3 in L2), orient = parity(k&14) ^ parity(lane&30) : gate 19 (qubit 6)
    {
        const int oL = __popc(lane & 30) & 1;
        const float2 tL  = oL ? gt[19] : gnt[19];   // when parity(k&14) even
        const float2 tLn = oL ? gnt[19] : gt[19];
#pragma unroll
        for (int k0 = 0; k0 < 16; k0++) {
            if ((k0 & 3) > 1) continue;
            const int k1 = k0 ^ 3;
            const int e = __popc(k0 & 14) & 1;      // compile-time
            const float2 ta_ = e ? tLn : tL;
            const float2 tb_ = e ? tL  : tLn;
            const float2 ar = re[k0], ai = im[k0], br = re[k1], bi = im[k1];
            re[k0] = f2fma(ta_, br, ar);
            im[k0] = f2fma(ta_, bi, ai);
            re[k1] = f2fma(tb_, ar, br);
            im[k1] = f2fma(tb_, ai, bi);
        }
    }

    // ==== measurement: sign = parity(i & 4927) ====
    // L2: lane bits {0(i4),1(i9),4(i12)} -> 19; k bits {0(i5),3(i8)} -> 9; + popc(warp)
    const float2 mn1 = make_float2(-1.f, -1.f);
    const int sgt = (__popc(lane & 19) + __popc(warp)) & 1;
    float2 acc = make_float2(0.f, 0.f);
#pragma unroll
    for (int k = 0; k < 16; k++) {
        const float2 p = f2fma(re[k], re[k], f2mul(im[k], im[k]));
        if (__popc(k & 9) & 1) acc = f2fma(p, mn1, acc);
        else                   acc = f2add(acc, p);
    }
    if (sgt) acc = f2mul(acc, mn1);
#pragma unroll
    for (int o = 16; o > 0; o >>= 1) {
        u64 av = *(u64*)&acc;
        u64 ov = __shfl_xor_sync(0xffffffffu, av, o);
        acc = f2add(acc, *(float2*)&ov);
        u64 sv = *(u64*)&ss;
        u64 so = __shfl_xor_sync(0xffffffffu, sv, o);
        ss = f2add(ss, *(float2*)&so);
    }
    if (lane == 0) { red[warp] = acc; red2[warp] = ss; }
    __syncthreads();                                             // BAR 3
    if (t == 0) {
        float2 ta = make_float2(0.f, 0.f);
        float2 ts = make_float2(0.f, 0.f);
#pragma unroll
        for (int r = 0; r < 16; r++) { ta = f2add(ta, red[r]); ts = f2add(ts, red2[r]); }
        const float C2 = Csq;
        out[2*b]   = C2 * ta.x / ts.x;
        out[2*b+1] = C2 * ta.y / ts.y;
    }
}

extern "C" void kernel_launch(void* const* d_in, const int* in_sizes, int n_in,
                              void* d_out, int out_size)
{
    const float* x = (const float*)d_in[0];
    const float* w = (const float*)d_in[1];
    float* out = (float*)d_out;
    const int B2 = (in_sizes[0] / DIM) / 2;        // 2 batch rows per CTA

    const size_t shmem = DIM * sizeof(float4);     // 128 KB
    cudaFuncSetAttribute(qc_kernel, cudaFuncAttributeMaxDynamicSharedMemorySize,
                         (int)shmem);
    qc_kernel<<<B2, 512, shmem>>>(x, w, out);      // single kernel
}

// round 16
// speedup vs baseline: 1.0097x; 1.0097x over previous
#include <cuda_runtime.h>

#define DIM 8192
typedef unsigned long long u64;

// ---- packed f32x2 helpers (SASS FFMA2/FMUL2 path, PTX-only) ----
__device__ __forceinline__ float2 f2fma(float2 a, float2 b, float2 c) {
    u64 r, au = *(u64*)&a, bu = *(u64*)&b, cu = *(u64*)&c;
    asm("fma.rn.f32x2 %0,%1,%2,%3;" : "=l"(r) : "l"(au), "l"(bu), "l"(cu));
    return *(float2*)&r;
}
__device__ __forceinline__ float2 f2mul(float2 a, float2 b) {
    u64 r, au = *(u64*)&a, bu = *(u64*)&b;
    asm("mul.rn.f32x2 %0,%1,%2;" : "=l"(r) : "l"(au), "l"(bu));
    return *(float2*)&r;
}
__device__ __forceinline__ float2 f2add(float2 a, float2 b) {
    u64 r, au = *(u64*)&a, bu = *(u64*)&b;
    asm("add.rn.f32x2 %0,%1,%2;" : "=l"(r) : "l"(au), "l"(bu));
    return *(float2*)&r;
}

// XOR-linear swizzle; bank(16B) = i0-2 ^ i4-6 ^ (i9<<1 | i10<<2).
// Conflict-free for all 6 structured access patterns below.
// XOR-linear over disjoint fields => phys(a|b) = phys(a) ^ phys(b).
__device__ constexpr int phys(int i) {
    return i ^ ((i >> 4) & 15) ^ ((i >> 8) & 6);
}

// Tangent-form RY rotation on register-bit BQ: out = (I + t*J) * in.
// Per-gate c = cos(theta/2) deferred into global C applied at measurement.
template<int BQ>
__device__ __forceinline__ void rotYt(float2 (&re)[16], float2 (&im)[16],
                                      float2 tg, float2 ntg) {
#pragma unroll
    for (int k0 = 0; k0 < 16; k0++) {
        if (k0 & (1 << BQ)) continue;
        const int k1 = k0 | (1 << BQ);
        const float2 r0 = re[k0], r1 = re[k1], i0 = im[k0], i1 = im[k1];
        re[k0] = f2fma(ntg, r1, r0);
        re[k1] = f2fma(tg,  r0, r1);
        im[k0] = f2fma(ntg, i1, i0);
        im[k1] = f2fma(tg,  i0, i1);
    }
}

__global__ void __launch_bounds__(512, 1)
qc_kernel(const float* __restrict__ x, const float* __restrict__ w,
          float* __restrict__ out)
{
    extern __shared__ float4 st[];                 // 8192 x (re-pack, im-pack) = 128 KB
    __shared__ float2 gt[26], gnt[26];             // tan(theta/2), packed dup (+/-)
    __shared__ float  gcs[26];                     // cos(theta/2) scalars (final C)
    __shared__ __align__(16) float2 tbl0s[16];     // A0 k-delta phases
    __shared__ __align__(16) float2 tbl1s[16];     // D01 k-delta (+Q,R) phases
    __shared__ float2 red[16], red2[16];

    const int t    = threadIdx.x;
    const int b    = blockIdx.x;                   // batch rows 2b, 2b+1
    const int lane = t & 31;
    const int warp = t >> 5;

    // ---- tables into smem (disjoint thread groups; visible after BAR1) ----
    if (t < 26) {
        const int l = t / 13, q = t - l * 13;
        float s, c; sincosf(0.5f * __ldg(&w[l*39 + q*3 + 1]), &s, &c);
        const float tn = s / c;
        gt[t]  = make_float2( tn,  tn);
        gnt[t] = make_float2(-tn, -tn);
        gcs[t] = c;
    } else if (t >= 64 && t < 80) {                 // A0 delta: i bits 0-3 -> phi0_{12..9}
        const int k = t - 64;
        float ang = 0.f;
        if (k & 1) ang += __ldg(&w[36]);
        if (k & 2) ang += __ldg(&w[33]);
        if (k & 4) ang += __ldg(&w[30]);
        if (k & 8) ang += __ldg(&w[27]);
        float s, c; __sincosf(ang, &s, &c);
        tbl0s[k] = make_float2(c, s);
    } else if (t >= 96 && t < 112) {                // D01 delta: omega0_{3..0} + Q,R terms
        const int k = t - 96;
        float ang = 0.f;
        if (k & 1) ang += __ldg(&w[11]);
        if (k & 2) ang += __ldg(&w[8]);
        if (k & 4) ang += __ldg(&w[5]);
        if (k & 8) ang += __ldg(&w[2]);
        ang += (__popc(k & 14) & 1) ?  0.5f*__ldg(&w[45]) : -0.5f*__ldg(&w[45]);
        ang += (__popc(k & 12) & 1) ?  0.5f*__ldg(&w[42]) : -0.5f*__ldg(&w[42]);
        float s, c; __sincosf(ang, &s, &c);
        tbl1s[k] = make_float2(c, s);
    }

    // ---- load two rows (layout A1: i = (t<<4)|k) via the read-only path.
    // Normalization deferred: carry ss = ||x||^2, divide at the end.
    float2 re[16], im[16];
    const float4* xp0 = reinterpret_cast<const float4*>(x + (size_t)(2*b)   * DIM + (t << 4));
    const float4* xp1 = reinterpret_cast<const float4*>(x + (size_t)(2*b+1) * DIM + (t << 4));
    float2 ss = make_float2(0.f, 0.f);
#pragma unroll
    for (int k4 = 0; k4 < 4; k4++) {
        const float4 v0 = __ldg(&xp0[k4]);
        const float4 v1 = __ldg(&xp1[k4]);
        re[k4*4+0] = make_float2(v0.x, v1.x);
        re[k4*4+1] = make_float2(v0.y, v1.y);
        re[k4*4+2] = make_float2(v0.z, v1.z);
        re[k4*4+3] = make_float2(v0.w, v1.w);
    }
#pragma unroll
    for (int k = 0; k < 16; k++) ss = f2fma(re[k], re[k], ss);

    // ---- per-thread phase bases (overlaps x-LDG latency) ----
    float b0a = -0.5f*(__ldg(&w[27]) + __ldg(&w[30]) + __ldg(&w[33]) + __ldg(&w[36]));
#pragma unroll
    for (int q = 0; q < 9; q++) {
        const float ph = __ldg(&w[3*q]);
        b0a += ((t >> (8 - q)) & 1) ? 0.5f*ph : -0.5f*ph;
    }
    float sb0, cb0; __sincosf(b0a, &sb0, &cb0);

    const int pt = (lane << 4) | warp;
    float bBa = -0.5f*(__ldg(&w[2]) + __ldg(&w[5]) + __ldg(&w[8]) + __ldg(&w[11]));
#pragma unroll
    for (int bb = 0; bb < 9; bb++) {
        const float om = __ldg(&w[3*(12 - bb) + 2]);
        bBa += ((pt >> bb) & 1) ? 0.5f*om : -0.5f*om;
    }
    const int PM[10] = {511,510,508,504,496,480,448,384,256,0};
    float Pv = 0.f;
#pragma unroll
    for (int tt = 0; tt < 10; tt++) {
        const float ph = __ldg(&w[75 - 3*tt]);
        Pv += (__popc(PM[tt] & pt) & 1) ? 0.5f*ph : -0.5f*ph;
    }
    const float Sv = (__popc(pt) & 1) ? 0.5f*__ldg(&w[39]) : -0.5f*__ldg(&w[39]);
    float sB, cB; __sincosf(bBa, &sB, &cB);
    float sP, cP; __sincosf(Pv,  &sP, &cP);
    float sS, cS; __sincosf(Sv,  &sS, &cS);
    const float t1r = cB*cP - sB*sP, t1i = cB*sP + sB*cP;
    const float t2r = cB*cP + sB*sP, t2i = sB*cP - cB*sP;
    const float w00r = t1r*cS - t1i*sS, w00i = t1r*sS + t1i*cS;
    const float w01r = t1r*cS + t1i*sS, w01i = t1i*cS - t1r*sS;
    const float w10r = t2r*cS - t2i*sS, w10i = t2r*sS + t2i*cS;
    const float w11r = t2r*cS + t2i*sS, w11i = t2i*cS - t2r*sS;

    // XOR-linear swizzled address bases (one LOP3 per access in the loops)
    const int pA1 = phys(t << 4);                                   // A1 store
    const int pA2 = phys((warp << 9) | ((lane & 16) << 4) | (lane & 15)); // A2 ld / C' st
    const int pCp = phys(pt);                                       // C' ld / L2 st
    const int pL2 = phys(((lane >> 1) << 9) | ((lane & 1) << 4) | warp); // L2 ld

    __syncthreads();   // BAR 1: tables visible (hidden under x-load latency)

    // ---- A0: layer-0 phi phase on the (unnormalized) real input ----
    const float4* tbl0f4 = reinterpret_cast<const float4*>(tbl0s);
#pragma unroll
    for (int kk = 0; kk < 8; kk++) {
        const float4 tb = tbl0f4[kk];
        {
            const int k0 = 2*kk;
            const float vr = cb0*tb.x - sb0*tb.y;
            const float vi = cb0*tb.y + sb0*tb.x;
            const float2 x0 = re[k0];
            re[k0] = f2mul(x0, make_float2(vr, vr));
            im[k0] = f2mul(x0, make_float2(vi, vi));
        }
        {
            const int k1 = 2*kk + 1;
            const float vr = cb0*tb.z - sb0*tb.w;
            const float vi = cb0*tb.w + sb0*tb.z;
            const float2 x1 = re[k1];
            re[k1] = f2mul(x1, make_float2(vr, vr));
            im[k1] = f2mul(x1, make_float2(vi, vi));
        }
    }

    // ==== LAYER 0 (tangent form) ====
    // pass A1: reg bits = i bits 0-3 (qubits 12..9)
    rotYt<0>(re, im, gt[12], gnt[12]);
    rotYt<1>(re, im, gt[11], gnt[11]);
    rotYt<2>(re, im, gt[10], gnt[10]);
    rotYt<3>(re, im, gt[ 9], gnt[ 9]);

    // warp-local exchange A1 -> A2 (reg bits = i bits 4-7)
#pragma unroll
    for (int k = 0; k < 16; k++)
        st[pA1 ^ phys(k)] = make_float4(re[k].x, re[k].y, im[k].x, im[k].y);
    __syncwarp();
#pragma unroll
    for (int k = 0; k < 16; k++) {
        const float4 v = st[pA2 ^ phys(k << 4)];
        re[k] = make_float2(v.x, v.y); im[k] = make_float2(v.z, v.w);
    }
    rotYt<0>(re, im, gt[8], gnt[8]);
    rotYt<1>(re, im, gt[7], gnt[7]);
    rotYt<2>(re, im, gt[6], gnt[6]);
    rotYt<3>(re, im, gt[5], gnt[5]);
    // shfl gate on i bit 8 (= lane bit 4), qubit 4
    {
        const float2 tSel = (lane & 16) ? gt[4] : gnt[4];
#pragma unroll
        for (int k = 0; k < 16; k++) {
            const u64 pr = __shfl_xor_sync(0xffffffffu, *(u64*)&re[k], 16);
            const u64 pi = __shfl_xor_sync(0xffffffffu, *(u64*)&im[k], 16);
            re[k] = f2fma(tSel, *(const float2*)&pr, re[k]);
            im[k] = f2fma(tSel, *(const float2*)&pi, im[k]);
        }
    }

    // block exchange A2 -> C' : i = (k<<9) | pt
#pragma unroll
    for (int k = 0; k < 16; k++)
        st[pA2 ^ phys(k << 4)] = make_float4(re[k].x, re[k].y, im[k].x, im[k].y);
    __syncthreads();                                             // BAR 2
#pragma unroll
    for (int k = 0; k < 16; k++) {
        const float4 v = st[pCp ^ phys(k << 9)];
        re[k] = make_float2(v.x, v.y); im[k] = make_float2(v.z, v.w);
    }
    // pass C': reg bits = i bits 9-12 (qubits 3..0)
    rotYt<0>(re, im, gt[3], gnt[3]);
    rotYt<1>(re, im, gt[2], gnt[2]);
    rotYt<2>(re, im, gt[1], gnt[1]);
    rotYt<3>(re, im, gt[0], gnt[0]);

    // ==== D01 diagonal: V[k] = W[s1(k)][s2(k)] * tbl1s[k] ====
    const float4* tbl1f4 = reinterpret_cast<const float4*>(tbl1s);
#pragma unroll
    for (int kk = 0; kk < 8; kk++) {
        const float4 tb = tbl1f4[kk];
#pragma unroll
        for (int h = 0; h < 2; h++) {
            const int k = 2*kk + h;
            const float tr_ = h ? tb.z : tb.x;
            const float ti_ = h ? tb.w : tb.y;
            const int s1 = __popc(k) & 1;
            const int s2 = __popc(k & 7) & 1;
            const float wr = s1 ? (s2 ? w11r : w10r) : (s2 ? w01r : w00r);
            const float wi = s1 ? (s2 ? w11i : w10i) : (s2 ? w01i : w00i);
            const float vr = wr*tr_ - wi*ti_;
            const float vi = wr*ti_ + wi*tr_;
            const float2 cd = make_float2(vr, vr);
            const float2 sd = make_float2(vi, vi);
            const float2 nd = make_float2(-vi, -vi);
            const float2 nr = f2fma(cd, re[k], f2mul(nd, im[k]));
            const float2 ni = f2fma(sd, re[k], f2mul(cd, im[k]));
            re[k] = nr; im[k] = ni;
        }
    }

    // ==== LAYER 1 (tangent form) ====
    // d12 = {11,12} (k-mask 12 in C'), orient = parity(i & 4095) : gate 13 (qubit 0)
    {
        const int Pt = __popc(pt) & 1;
#pragma unroll
        for (int k0 = 0; k0 < 8; k0++) {
            const int k1 = k0 ^ 12;
            const int o = Pt ^ (__popc(k0 & 7) & 1);
            const float2 ta_ = o ? gt[13] : gnt[13];
            const float2 tb_ = o ? gnt[13] : gt[13];
            const float2 ar = re[k0], ai = im[k0], br = re[k1], bi = im[k1];
            re[k0] = f2fma(ta_, br, ar);
            im[k0] = f2fma(ta_, bi, ai);
            re[k1] = f2fma(tb_, ar, br);
            im[k1] = f2fma(tb_, ai, bi);
        }
    }
    // d10 = {9,10} (k-mask 3 in C'), orient = parity(k & 14) : gate 15 (qubit 2)
    {
#pragma unroll
        for (int k0 = 0; k0 < 16; k0++) {
            if ((k0 & 3) > 1) continue;
            const int k1 = k0 ^ 3;
            const int o = __popc(k0 & 14) & 1;
            const float2 ta_ = o ? gt[15] : gnt[15];
            const float2 tb_ = o ? gnt[15] : gt[15];
            const float2 ar = re[k0], ai = im[k0], br = re[k1], bi = im[k1];
            re[k0] = f2fma(ta_, br, ar);
            im[k0] = f2fma(ta_, bi, ai);
            re[k1] = f2fma(tb_, ar, br);
            im[k1] = f2fma(tb_, ai, bi);
        }
    }

    // ==== warp-local exchange C' -> L2 (warp-private slots; syncwarp only) ====
    // L2: reg k = i bits 5-8; lane bit0 = i4, lane bits 1-4 = i bits 9-12
#pragma unroll
    for (int k = 0; k < 16; k++)
        st[pCp ^ phys(k << 9)] = make_float4(re[k].x, re[k].y, im[k].x, im[k].y);
    __syncwarp();
#pragma unroll
    for (int k = 0; k < 16; k++) {
        const float4 v = st[pL2 ^ phys(k << 5)];
        re[k] = make_float2(v.x, v.y); im[k] = make_float2(v.z, v.w);
    }

    // d8 = {7,8} (k-mask 12 in L2), orient = i8 ^ parity(i9-12) : gate 17 (qubit 4)
    {
        const int oL = __popc(lane & 30) & 1;
        const float2 ta_ = oL ? gt[17] : gnt[17];
        const float2 tb_ = oL ? gnt[17] : gt[17];
#pragma unroll
        for (int k0 = 0; k0 < 8; k0++) {
            const int k1 = k0 ^ 12;
            const float2 ar = re[k0], ai = im[k0], br = re[k1], bi = im[k1];
            re[k0] = f2fma(ta_, br, ar);
            im[k0] = f2fma(ta_, bi, ai);
            re[k1] = f2fma(tb_, ar, br);
            im[k1] = f2fma(tb_, ai, bi);
        }
    }
    // d6 = {5,6} (k-mask 3 in L2), orient = parity(k&14) ^ parity(lane&30) : gate 19 (qubit 6)
    {
        const int oL = __popc(lane & 30) & 1;
#pragma unroll
        for (int k0 = 0; k0 < 16; k0++) {
            if ((k0 & 3) > 1) continue;
            const int k1 = k0 ^ 3;
            const int o = oL ^ (__popc(k0 & 14) & 1);
            const float2 ta_ = o ? gt[19] : gnt[19];
            const float2 tb_ = o ? gnt[19] : gt[19];
            const float2 ar = re[k0], ai = im[k0], br = re[k1], bi = im[k1];
            re[k0] = f2fma(ta_, br, ar);
            im[k0] = f2fma(ta_, bi, ai);
            re[k1] = f2fma(tb_, ar, br);
            im[k1] = f2fma(tb_, ai, bi);
        }
    }

    // ==== measurement: sign = parity(i & 4927) ====
    // L2: lane bits {0(i4),1(i9),4(i12)} -> 19; k bits {0(i5),3(i8)} -> 9; + popc(warp)
    const float2 mn1 = make_float2(-1.f, -1.f);
    const int sgt = (__popc(lane & 19) + __popc(warp)) & 1;
    float2 acc = make_float2(0.f, 0.f);
#pragma unroll
    for (int k = 0; k < 16; k++) {
        const float2 p = f2fma(re[k], re[k], f2mul(im[k], im[k]));
        if (__popc(k & 9) & 1) acc = f2fma(p, mn1, acc);
        else                   acc = f2add(acc, p);
    }
    if (sgt) acc = f2mul(acc, mn1);
#pragma unroll
    for (int o = 16; o > 0; o >>= 1) {
        u64 av = *(u64*)&acc;
        u64 ov = __shfl_xor_sync(0xffffffffu, av, o);
        acc = f2add(acc, *(float2*)&ov);
        u64 sv = *(u64*)&ss;
        u64 so = __shfl_xor_sync(0xffffffffu, sv, o);
        ss = f2add(ss, *(float2*)&so);
    }
    if (lane == 0) { red[warp] = acc; red2[warp] = ss; }
    __syncthreads();                                             // BAR 3
    if (t == 0) {
        float2 ta = make_float2(0.f, 0.f);
        float2 ts = make_float2(0.f, 0.f);
#pragma unroll
        for (int r = 0; r < 16; r++) { ta = f2add(ta, red[r]); ts = f2add(ts, red2[r]); }
        float C = 1.f;
#pragma unroll
        for (int g = 0; g < 13; g++) C *= gcs[g];
        C *= gcs[13] * gcs[15] * gcs[17] * gcs[19];
        const float C2 = C * C;
        out[2*b]   = C2 * ta.x / ts.x;
        out[2*b+1] = C2 * ta.y / ts.y;
    }
}

extern "C" void kernel_launch(void* const* d_in, const int* in_sizes, int n_in,
                              void* d_out, int out_size)
{
    const float* x = (const float*)d_in[0];
    const float* w = (const float*)d_in[1];
    float* out = (float*)d_out;
    const int B2 = (in_sizes[0] / DIM) / 2;        // 2 batch rows per CTA

    const size_t shmem = DIM * sizeof(float4);     // 128 KB
    cudaFuncSetAttribute(qc_kernel, cudaFuncAttributeMaxDynamicSharedMemorySize,
                         (int)shmem);
    qc_kernel<<<B2, 512, shmem>>>(x, w, out);      // single kernel
}